// round 15
// baseline (speedup 1.0000x reference)
#include <cuda_runtime.h>
#include <cuda_bf16.h>
#include <math.h>
#include <stdint.h>

// ---------------- problem constants ----------------
#define ROWS 4096        // B*N
#define CDIM 512
#define QKVD 1536
#define HID  2048
#define NHEAD 8
#define HD   64
#define NQ   1024
#define BHN  32768       // B*H*N
#define NBKT 81
#define LSTR 88          // bf16 LK row stride (16B-aligned)

// ---------------- device scratch ----------------
__device__ float g_ln    [2][ROWS*CDIM];
__device__ float g_qkv   [2][ROWS*QKVD];
__device__ float g_att   [2][ROWS*CDIM];
__device__ __nv_bfloat16 g_lkb [2][(size_t)BHN*LSTR];
__device__ __nv_bfloat16 g_lqt [2][(size_t)32*NBKT*NQ];   // transposed: [bh][c][j]
__device__ float g_logits[2][(size_t)32*NQ*NQ];
__device__ float g_ml    [2][BHN];
__device__ float g_hid   [2][(size_t)ROWS*HID];

__constant__ signed char c_pidx[63] = {
  -4,-4,-4,-4,-4,-4,-4,-4,-4,-4,-4,-4,-4,-4,-4,-4,-4,-4,-4,-4,-4,
  -3,-3,-3,-3,-3,-3,-3,
  -2,-2,
  -1,
   0,
   1,
   2, 2,
   3, 3, 3, 3, 3, 3, 3,
   4, 4, 4, 4, 4, 4, 4, 4, 4, 4, 4, 4, 4, 4, 4, 4, 4, 4, 4, 4, 4
};

__device__ __forceinline__ float fexp(float x){
  float y = x * 1.4426950408889634f;
  float n = rintf(y);
  float f = y - n;
  float p =           1.3333558e-3f;
  p = fmaf(p, f, 9.6181291e-3f);
  p = fmaf(p, f, 5.5504108e-2f);
  p = fmaf(p, f, 2.4022650e-1f);
  p = fmaf(p, f, 6.9314718e-1f);
  p = fmaf(p, f, 1.0f);
  int ni = (int)n;
  return p * __int_as_float((ni + 127) << 23);
}

__device__ __forceinline__ uint32_t f2tf32(float v){
  uint32_t r;
  asm("cvt.rna.tf32.f32 %0, %1;" : "=r"(r) : "f"(v));
  return r;
}

__device__ __forceinline__ void mma_tf32(float* c, const uint32_t* a, const uint32_t* b){
  asm volatile(
    "mma.sync.aligned.m16n8k8.row.col.f32.tf32.tf32.f32 "
    "{%0,%1,%2,%3}, {%4,%5,%6,%7}, {%8,%9}, {%0,%1,%2,%3};"
    : "+f"(c[0]), "+f"(c[1]), "+f"(c[2]), "+f"(c[3])
    : "r"(a[0]), "r"(a[1]), "r"(a[2]), "r"(a[3]), "r"(b[0]), "r"(b[1]));
}

__device__ __forceinline__ void cp16(uint32_t dst, const void* src){
  asm volatile("cp.async.cg.shared.global [%0], [%1], 16;\n" :: "r"(dst), "l"(src));
}

struct GemmPtrs {
  const float* A[2];
  const float* B[2];
  const float* bias[2];
  const float* resid[2];
  float* C[2];
};

// ---------------- layernorm (paired streams) --------------------------------
__global__ void ln_kernel(const float* __restrict__ x0, const float* __restrict__ x1,
                          const float* __restrict__ g0, const float* __restrict__ g1,
                          const float* __restrict__ be0, const float* __restrict__ be1,
                          float* __restrict__ y0, float* __restrict__ y1)
{
  int sIdx = blockIdx.y;
  const float* x  = sIdx ? x1 : x0;
  const float* gam= sIdx ? g1 : g0;
  const float* bet= sIdx ? be1 : be0;
  float* y        = sIdx ? y1 : y0;
  int row = blockIdx.x;
  int t = threadIdx.x;
  const float* xr = x + (size_t)row * CDIM;
  float4 v = *(const float4*)(xr + t*4);
  float s  = v.x + v.y + v.z + v.w;
  float s2 = v.x*v.x + v.y*v.y + v.z*v.z + v.w*v.w;
  #pragma unroll
  for (int o = 16; o > 0; o >>= 1){
    s  += __shfl_xor_sync(0xffffffffu, s , o);
    s2 += __shfl_xor_sync(0xffffffffu, s2, o);
  }
  __shared__ float rs[4], rq[4];
  if ((t & 31) == 0){ rs[t>>5] = s; rq[t>>5] = s2; }
  __syncthreads();
  s  = rs[0]+rs[1]+rs[2]+rs[3];
  s2 = rq[0]+rq[1]+rq[2]+rq[3];
  float mu   = s  * (1.0f/CDIM);
  float var  = s2 * (1.0f/CDIM) - mu*mu;
  float rstd = rsqrtf(var + 1e-5f);
  float4 g4 = *(const float4*)(gam + t*4);
  float4 b4 = *(const float4*)(bet + t*4);
  float4 o4;
  o4.x = (v.x-mu)*rstd*g4.x + b4.x;
  o4.y = (v.y-mu)*rstd*g4.y + b4.y;
  o4.z = (v.z-mu)*rstd*g4.z + b4.z;
  o4.w = (v.w-mu)*rstd*g4.w + b4.w;
  *(float4*)(y + (size_t)row*CDIM + t*4) = o4;
}

// ---------------- tf32 GEMM, cp.async double-buffered, BN templated --------
template <int BN>
__global__ void __launch_bounds__(256, 2) sgemm_tf32_kernel(
    GemmPtrs p, int M, int N, int K, int gelu)
{
  constexpr int BSTR = BN + 4;
  constexpr int MT = (BN == 128) ? 4 : 2;
  constexpr int NT = 4;
  constexpr int NBCH = (BN == 128) ? 2 : 1;
  __shared__ float As[2][128*20];
  __shared__ float Bs[2][16*BSTR];
  int t = threadIdx.x;
  int z = blockIdx.z;
  const float* A     = p.A[z];
  const float* Bm    = p.B[z];
  const float* bias  = p.bias[z];
  const float* resid = p.resid[z];
  float* C           = p.C[z];

  int bn = blockIdx.x * BN;
  int bm = blockIdx.y * 128;
  int warp = t >> 5, lane = t & 31;
  int wm, wn;
  if (BN == 128){ wm = (warp >> 2) << 6; wn = (warp & 3) << 5; }
  else          { wm = (warp >> 1) << 5; wn = (warp & 1) << 5; }
  int g  = lane >> 2;
  int tg = lane & 3;

  float acc[MT][NT][4];
  #pragma unroll
  for (int mt=0;mt<MT;mt++)
    #pragma unroll
    for (int nt=0;nt<NT;nt++)
      #pragma unroll
      for (int c=0;c<4;c++) acc[mt][nt][c] = 0.f;

  const float* Ag = A + (size_t)bm * K;
  const float* Bg = Bm + bn;

  uint32_t asb[2], bsb[2];
  asb[0] = (uint32_t)__cvta_generic_to_shared(&As[0][0]);
  asb[1] = (uint32_t)__cvta_generic_to_shared(&As[1][0]);
  bsb[0] = (uint32_t)__cvta_generic_to_shared(&Bs[0][0]);
  bsb[1] = (uint32_t)__cvta_generic_to_shared(&Bs[1][0]);

  int ar[2], as4[2], bkr[NBCH], bnc[NBCH];
  #pragma unroll
  for (int i = 0; i < 2; i++){
    int c = t + (i<<8);
    ar[i]  = c >> 2;  as4[i] = (c & 3) << 2;
  }
  #pragma unroll
  for (int i = 0; i < NBCH; i++){
    int c = t + (i<<8);
    if (BN == 128){ bkr[i] = c >> 5; bnc[i] = (c & 31) << 2; }
    else          { bkr[i] = c >> 4; bnc[i] = (c & 15) << 2; }
  }

  int ntiles = K >> 4;
  #pragma unroll
  for (int i = 0; i < 2; i++)
    cp16(asb[0] + ((ar[i]*20 + as4[i])<<2), Ag + (size_t)ar[i]*K + as4[i]);
  #pragma unroll
  for (int i = 0; i < NBCH; i++)
    cp16(bsb[0] + ((bkr[i]*BSTR + bnc[i])<<2), Bg + (size_t)bkr[i]*N + bnc[i]);
  asm volatile("cp.async.commit_group;\n");

  for (int it = 0; it < ntiles; it++){
    int buf = it & 1;
    if (it + 1 < ntiles){
      int k0 = (it+1) << 4;
      int nb = (it+1) & 1;
      #pragma unroll
      for (int i = 0; i < 2; i++)
        cp16(asb[nb] + ((ar[i]*20 + as4[i])<<2), Ag + (size_t)ar[i]*K + k0 + as4[i]);
      #pragma unroll
      for (int i = 0; i < NBCH; i++)
        cp16(bsb[nb] + ((bkr[i]*BSTR + bnc[i])<<2), Bg + (size_t)(k0 + bkr[i])*N + bnc[i]);
    }
    asm volatile("cp.async.commit_group;\n");
    asm volatile("cp.async.wait_group 1;\n");
    __syncthreads();

    const float* Ab = As[buf];
    const float* Bb = Bs[buf];
    #pragma unroll
    for (int ks = 0; ks < 16; ks += 8){
      uint32_t af[MT][4], bf[NT][2];
      #pragma unroll
      for (int mt = 0; mt < MT; mt++){
        int m = wm + (mt<<4) + g;
        af[mt][0] = __float_as_uint(Ab[ m   *20 + ks+tg  ]);
        af[mt][1] = __float_as_uint(Ab[(m+8)*20 + ks+tg  ]);
        af[mt][2] = __float_as_uint(Ab[ m   *20 + ks+tg+4]);
        af[mt][3] = __float_as_uint(Ab[(m+8)*20 + ks+tg+4]);
      }
      #pragma unroll
      for (int nt = 0; nt < NT; nt++){
        int n = wn + (nt<<3) + g;
        bf[nt][0] = __float_as_uint(Bb[(ks+tg  )*BSTR + n]);
        bf[nt][1] = __float_as_uint(Bb[(ks+tg+4)*BSTR + n]);
      }
      #pragma unroll
      for (int mt = 0; mt < MT; mt++)
        #pragma unroll
        for (int nt = 0; nt < NT; nt++)
          mma_tf32(acc[mt][nt], af[mt], bf[nt]);
    }
    __syncthreads();
  }

  #pragma unroll
  for (int mt = 0; mt < MT; mt++){
    int row0 = bm + wm + (mt<<4) + g;
    #pragma unroll
    for (int nt = 0; nt < NT; nt++){
      int col = bn + wn + (nt<<3) + (tg<<1);
      float b0 = bias[col], b1 = bias[col+1];
      #pragma unroll
      for (int h = 0; h < 2; h++){
        int row = row0 + (h<<3);
        float r0 = acc[mt][nt][h*2+0] + b0;
        float r1 = acc[mt][nt][h*2+1] + b1;
        if (gelu){
          r0 = 0.5f*r0*(1.0f + erff(r0*0.70710678f));
          r1 = 0.5f*r1*(1.0f + erff(r1*0.70710678f));
        }
        if (resid){
          const float2 rr = *(const float2*)(resid + (size_t)row*N + col);
          r0 += rr.x; r1 += rr.y;
        }
        *(float2*)(C + (size_t)row*N + col) = make_float2(r0, r1);
      }
    }
  }
}

// ---------------- bias tables: LK row-major bf16, LQ transposed bf16 -------
__global__ void __launch_bounds__(256) biastab_kernel(
    const float* __restrict__ qkv0, const float* __restrict__ qkv1,
    const float* __restrict__ tq, const float* __restrict__ tk,
    __nv_bfloat16* __restrict__ lk0, __nv_bfloat16* __restrict__ lk1,
    __nv_bfloat16* __restrict__ lqt0, __nv_bfloat16* __restrict__ lqt1)
{
  __shared__ float qs[64*65];
  __shared__ float tabT[64*84];
  __shared__ __nv_bfloat16 trans[NBKT*68];

  int t = threadIdx.x;
  int s = blockIdx.z, which = blockIdx.y;
  int base = blockIdx.x << 6;
  const float* src;
  float scl;
  if (which == 0){ src = (s == 0 ? qkv0 : qkv1);       scl = 1.0f;   }
  else           { src = (s == 0 ? qkv1 : qkv0) + 512; scl = 0.125f; }
  const float* tab = (which == 0) ? tk : tq;

  for (int idx = t; idx < NBKT*64; idx += 256){
    int c = idx >> 6, d = idx & 63;
    tabT[d*84 + c] = tab[idx];
  }
  #pragma unroll
  for (int it = 0; it < 4; it++){
    int f = t + (it<<8);
    int r = f >> 4, c4 = (f & 15) << 2;
    int rid = base + r;
    int bh = rid >> 10, n = rid & 1023;
    int b = bh >> 3, h = bh & 7;
    float4 v = *(const float4*)(src + (size_t)((b<<10)+n)*QKVD + (h<<6) + c4);
    qs[r*65+c4+0] = scl*v.x; qs[r*65+c4+1] = scl*v.y;
    qs[r*65+c4+2] = scl*v.z; qs[r*65+c4+3] = scl*v.w;
  }
  __syncthreads();

  int tx = t & 31, ty = t >> 5;
  float acc[8][3];
  #pragma unroll
  for (int i=0;i<8;i++){ acc[i][0]=0.f; acc[i][1]=0.f; acc[i][2]=0.f; }

  #pragma unroll 8
  for (int k = 0; k < 64; k++){
    float b0 = tabT[k*84 + tx];
    float b1 = tabT[k*84 + tx + 32];
    float b2 = (tx < 17) ? tabT[k*84 + tx + 64] : 0.f;
    #pragma unroll
    for (int i = 0; i < 8; i++){
      float a = qs[((ty<<3)+i)*65 + k];
      acc[i][0] = fmaf(a, b0, acc[i][0]);
      acc[i][1] = fmaf(a, b1, acc[i][1]);
      acc[i][2] = fmaf(a, b2, acc[i][2]);
    }
  }

  if (which == 0){
    __nv_bfloat16* dstbase = (s == 0 ? lk0 : lk1);
    #pragma unroll
    for (int i = 0; i < 8; i++){
      int rid = base + (ty<<3) + i;
      __nv_bfloat16* dst = dstbase + (size_t)rid*LSTR;
      dst[tx]      = __float2bfloat16(acc[i][0]);
      dst[tx + 32] = __float2bfloat16(acc[i][1]);
      if (tx < 17) dst[tx + 64] = __float2bfloat16(acc[i][2]);
    }
  } else {
    // transpose via smem, then coalesced row writes: lqt[bh][c][n]
    #pragma unroll
    for (int i = 0; i < 8; i++){
      int nloc = (ty<<3) + i;
      trans[tx*68 + nloc]      = __float2bfloat16(acc[i][0]);
      trans[(tx+32)*68 + nloc] = __float2bfloat16(acc[i][1]);
      if (tx < 17) trans[(tx+64)*68 + nloc] = __float2bfloat16(acc[i][2]);
    }
    __syncthreads();
    int bh = base >> 10, n0 = base & 1023;
    __nv_bfloat16* dstT = (s == 0 ? lqt0 : lqt1) + ((size_t)bh*NBKT)*NQ + n0;
    for (int f = t; f < NBKT*64; f += 256){
      int c = f >> 6, n = f & 63;
      dstT[(size_t)c*NQ + n] = trans[c*68 + n];
    }
  }
}

// ---------------- strip logits: mma -> ps tile -> run-based bias pass ------
// smem floats: qs[4160]@0, ks 2x[4352]@4160, lks(2816f)@12864,
//              lqt 2x(2916f)@15680, ps[4352]@21512 ; total 25864 floats
#define LG_QS   0
#define LG_KS   4160
#define LG_KSZ  4352
#define LG_LKS  12864
#define LG_LQT  15680
#define LG_LQZ  2916
#define LG_PS   21512
#define LG_SMEM_FLOATS 25864

__global__ void __launch_bounds__(256, 2) logits_kernel(
    const float* __restrict__ qkv0, const float* __restrict__ qkv1,
    const __nv_bfloat16* __restrict__ lk0, const __nv_bfloat16* __restrict__ lk1,
    const __nv_bfloat16* __restrict__ lqt0, const __nv_bfloat16* __restrict__ lqt1,
    float* __restrict__ lg0, float* __restrict__ lg1,
    float* __restrict__ ml0, float* __restrict__ ml1)
{
  extern __shared__ float sm[];
  float* qs = sm + LG_QS;
  __nv_bfloat16* lks = (__nv_bfloat16*)(sm + LG_LKS);
  float* ps = sm + LG_PS;

  int t = threadIdx.x;
  int zs = blockIdx.y;
  int s = zs >> 5;
  int bh = zs & 31; int b = bh>>3, h = bh&7;
  int i0 = blockIdx.x << 6;
  size_t rbase = ((size_t)bh)<<10;

  const float* qkv_q  = (s==0) ? qkv0 : qkv1;
  const float* qkv_kv = (s==0) ? qkv1 : qkv0;
  const __nv_bfloat16* LKb  = (s==0) ? lk0  : lk1;
  const __nv_bfloat16* LQTb = ((s==0) ? lqt0 : lqt1) + ((size_t)bh*NBKT)*NQ;
  float* S  = (s==0) ? lg0 : lg1;
  float* ML = (s==0) ? ml0 : ml1;

  const float* qb = qkv_q  + (size_t)(b<<10)*QKVD + (h<<6);
  const float* kb = qkv_kv + (size_t)(b<<10)*QKVD + (h<<6) + 512;

  uint32_t ksb[2], lqtb[2];
  ksb[0]  = (uint32_t)__cvta_generic_to_shared(sm + LG_KS);
  ksb[1]  = (uint32_t)__cvta_generic_to_shared(sm + LG_KS + LG_KSZ);
  lqtb[0] = (uint32_t)__cvta_generic_to_shared(sm + LG_LQT);
  lqtb[1] = (uint32_t)__cvta_generic_to_shared(sm + LG_LQT + LG_LQZ);
  uint32_t lksb = (uint32_t)__cvta_generic_to_shared(sm + LG_LKS);

  // prologue: lks (once, rows of 88 bf16 = 11 chunks), K tile0, lqT tile0
  for (int f = t; f < 704; f += 256){
    int r = f / 11, c8 = (f - r*11) << 3;
    cp16(lksb + ((r*LSTR + c8)<<1), LKb + (rbase + i0 + r)*LSTR + c8);
  }
  #pragma unroll
  for (int i = 0; i < 4; i++){
    int f = t + (i<<8);
    int r = f >> 4, c4 = (f & 15) << 2;
    cp16(ksb[0] + ((r*68 + c4)<<2), kb + (size_t)r*QKVD + c4);
  }
  for (int f = t; f < 648; f += 256){      // 81 rows x 8 chunks (64 bf16/row)
    int c = f >> 3, ch = f & 7;
    cp16(lqtb[0] + c*144 + (ch<<4), LQTb + (size_t)c*NQ + (ch<<3));
  }
  asm volatile("cp.async.commit_group;\n");

  // Q staged synchronously (once)
  #pragma unroll
  for (int it = 0; it < 4; it++){
    int f = t + (it<<8);
    int r = f >> 4, c4 = (f & 15) << 2;
    float4 qv = *(const float4*)(qb + (size_t)(i0+r)*QKVD + c4);
    qs[r*65+c4+0]=qv.x; qs[r*65+c4+1]=qv.y;
    qs[r*65+c4+2]=qv.z; qs[r*65+c4+3]=qv.w;
  }

  int warp = t >> 5, lane = t & 31;
  int g = lane >> 2, tg = lane & 3;
  int wm = (warp >> 2) << 5;
  int wn = (warp & 3) << 4;

  int sr = t >> 2;                 // epilogue row
  int q0 = (t & 3) << 4;           // 16 consecutive j
  int yi = (i0 + sr) >> 5, xi = (i0 + sr) & 31;
  const __nv_bfloat16* lkrow = lks + sr*LSTR;
  float rml = -1e30f;

  for (int jt = 0; jt < 16; jt++){
    int buf = jt & 1;
    if (jt + 1 < 16){
      int j0n = (jt+1) << 6;
      int nb = (jt+1) & 1;
      #pragma unroll
      for (int i = 0; i < 4; i++){
        int f = t + (i<<8);
        int r = f >> 4, c4 = (f & 15) << 2;
        cp16(ksb[nb] + ((r*68 + c4)<<2), kb + (size_t)(j0n+r)*QKVD + c4);
      }
      for (int f = t; f < 648; f += 256){
        int c = f >> 3, ch = f & 7;
        cp16(lqtb[nb] + c*144 + (ch<<4), LQTb + (size_t)c*NQ + j0n + (ch<<3));
      }
    }
    asm volatile("cp.async.commit_group;\n");
    asm volatile("cp.async.wait_group 1;\n");
    __syncthreads();

    const float* ks = sm + LG_KS + buf*LG_KSZ;
    const __nv_bfloat16* lqt = (const __nv_bfloat16*)(sm + LG_LQT + buf*LG_LQZ);
    int j0 = jt << 6;

    float acc[2][2][4];
    #pragma unroll
    for (int mt=0;mt<2;mt++)
      #pragma unroll
      for (int nt=0;nt<2;nt++)
        #pragma unroll
        for (int c=0;c<4;c++) acc[mt][nt][c]=0.f;

    #pragma unroll
    for (int kk = 0; kk < 64; kk += 8){
      uint32_t af[2][4], bf[2][2];
      #pragma unroll
      for (int mt = 0; mt < 2; mt++){
        int r0 = wm + (mt<<4) + g;
        af[mt][0] = __float_as_uint(qs[ r0   *65 + kk+tg  ]);
        af[mt][1] = __float_as_uint(qs[(r0+8)*65 + kk+tg  ]);
        af[mt][2] = __float_as_uint(qs[ r0   *65 + kk+tg+4]);
        af[mt][3] = __float_as_uint(qs[(r0+8)*65 + kk+tg+4]);
      }
      #pragma unroll
      for (int nt = 0; nt < 2; nt++){
        int n = wn + (nt<<3) + g;
        bf[nt][0] = __float_as_uint(ks[n*68 + kk+tg  ]);
        bf[nt][1] = __float_as_uint(ks[n*68 + kk+tg+4]);
      }
      #pragma unroll
      for (int mt = 0; mt < 2; mt++)
        #pragma unroll
        for (int nt = 0; nt < 2; nt++)
          mma_tf32(acc[mt][nt], af[mt], bf[nt]);
    }

    // dump raw scores (scaled) into ps tile
    #pragma unroll
    for (int mt = 0; mt < 2; mt++){
      #pragma unroll
      for (int hh = 0; hh < 2; hh++){
        int il = wm + (mt<<4) + g + (hh<<3);
        #pragma unroll
        for (int nt = 0; nt < 2; nt++){
          int jl = wn + (nt<<3) + (tg<<1);
          *(float2*)&ps[il*68 + jl] =
              make_float2(acc[mt][nt][hh*2+0]*0.125f, acc[mt][nt][hh*2+1]*0.125f);
        }
      }
    }
    __syncthreads();

    // run-based bias pass: row sr, 16 consecutive j
    {
      float vbuf[16];
      int runb = -1;
      float lkv = 0.f;
      #pragma unroll
      for (int q = 0; q < 16; q++){
        int j = j0 + q0 + q;
        int dy = yi - (j>>5), dx = xi - (j&31);
        int bkt = ((int)c_pidx[dy+31]+4)*9 + ((int)c_pidx[dx+31]+4);
        if (bkt != runb){ lkv = __bfloat162float(lkrow[bkt]); runb = bkt; }
        float v = ps[sr*68 + q0 + q] + lkv
                + __bfloat162float(lqt[(80 - bkt)*72 + q0 + q]);
        vbuf[q] = v;
        rml = fmaxf(rml, v);
      }
      float4* So = (float4*)(S + (rbase + i0 + sr)*NQ + j0 + q0);
      So[0] = make_float4(vbuf[0], vbuf[1], vbuf[2], vbuf[3]);
      So[1] = make_float4(vbuf[4], vbuf[5], vbuf[6], vbuf[7]);
      So[2] = make_float4(vbuf[8], vbuf[9], vbuf[10], vbuf[11]);
      So[3] = make_float4(vbuf[12], vbuf[13], vbuf[14], vbuf[15]);
    }
    __syncthreads();
  }

  // row max: reduce over the 4 lanes sharing sr, write directly
  rml = fmaxf(rml, __shfl_xor_sync(0xffffffffu, rml, 1));
  rml = fmaxf(rml, __shfl_xor_sync(0xffffffffu, rml, 2));
  if ((t & 3) == 0) ML[rbase + i0 + sr] = rml;
}

// ---------------- PV: cp.async double-buffered + scatter + tv-GEMM ---------
#define PV_S    0
#define PV_V    8704
#define PV_SB   17408
#define PV_MROW 23040
#define PV_RSV  23104
#define PV_TVS  8704
#define PV_SMEM_FLOATS 23168

__global__ void __launch_bounds__(256) pv_kernel(
    const float* __restrict__ lg0, const float* __restrict__ lg1,
    const float* __restrict__ ml0, const float* __restrict__ ml1,
    const float* __restrict__ qkv0, const float* __restrict__ qkv1,
    const float* __restrict__ tv,
    float* __restrict__ att0, float* __restrict__ att1)
{
  extern __shared__ float sm[];
  float* sb  = sm + PV_SB;
  float* mrow= sm + PV_MROW;
  float* rsv = sm + PV_RSV;

  int t = threadIdx.x;
  int zy = blockIdx.y;
  int s = zy >> 5;
  int bh = zy & 31; int b = bh>>3, h = bh&7;
  int i0 = blockIdx.x << 6;
  size_t rb2 = (((size_t)bh)<<10) + i0;

  const float* S  = (s==0) ? lg0 : lg1;
  const float* ml = (s==0) ? ml0 : ml1;
  const float* qkv_kv = (s==0) ? qkv1 : qkv0;
  float* out = (s==0) ? att0 : att1;

  if (t < 64) mrow[t] = ml[rb2 + t];
  for (int f = t; f < 64*88; f += 256) sb[f] = 0.f;

  const float* vb = qkv_kv + ((size_t)(b<<10))*QKVD + (h<<6) + 1024;

  uint32_t sbs[2], vbs[2];
  sbs[0] = (uint32_t)__cvta_generic_to_shared(sm + PV_S);
  sbs[1] = (uint32_t)__cvta_generic_to_shared(sm + PV_S + 4352);
  vbs[0] = (uint32_t)__cvta_generic_to_shared(sm + PV_V);
  vbs[1] = (uint32_t)__cvta_generic_to_shared(sm + PV_V + 4352);

  int cr[4], cc4[4];
  #pragma unroll
  for (int i = 0; i < 4; i++){
    int f = t + (i<<8);
    cr[i] = f >> 4; cc4[i] = (f & 15) << 2;
  }

  #pragma unroll
  for (int i = 0; i < 4; i++){
    cp16(sbs[0] + ((cr[i]*68 + cc4[i])<<2), S + (rb2 + cr[i])*NQ + cc4[i]);
    cp16(vbs[0] + ((cr[i]*68 + cc4[i])<<2), vb + (size_t)cr[i]*QKVD + cc4[i]);
  }
  asm volatile("cp.async.commit_group;\n");
  __syncthreads();

  int warp = t >> 5, lane = t & 31;
  int g = lane >> 2, tg = lane & 3;
  int wm = (warp >> 2) << 5;
  int wn = (warp & 3) << 4;

  float acc[2][2][4];
  #pragma unroll
  for (int mt=0;mt<2;mt++)
    #pragma unroll
    for (int nt=0;nt<2;nt++)
      #pragma unroll
      for (int c=0;c<4;c++) acc[mt][nt][c]=0.f;

  int sr = t >> 2;
  int q0 = (t & 3) << 4;
  int iglob = i0 + sr;
  int syi = iglob >> 5, sxi = iglob & 31;
  float msr = mrow[sr];

  for (int jt = 0; jt < 16; jt++){
    int buf = jt & 1;
    if (jt + 1 < 16){
      int j0n = (jt+1) << 6;
      int nb = (jt+1) & 1;
      #pragma unroll
      for (int i = 0; i < 4; i++){
        cp16(sbs[nb] + ((cr[i]*68 + cc4[i])<<2), S + (rb2 + cr[i])*NQ + j0n + cc4[i]);
        cp16(vbs[nb] + ((cr[i]*68 + cc4[i])<<2), vb + (size_t)(j0n + cr[i])*QKVD + cc4[i]);
      }
    }
    asm volatile("cp.async.commit_group;\n");
    asm volatile("cp.async.wait_group 1;\n");
    __syncthreads();

    float* ps = sm + PV_S + buf*4352;
    float* vs = sm + PV_V + buf*4352;
    int j0 = jt << 6;

    {
      float runv = 0.f; int runb = -1;
      #pragma unroll
      for (int q = 0; q < 16; q++){
        int jj = q0 + q;
        int idx = sr*68 + jj;
        float pvv = __uint_as_float(f2tf32(fexp(ps[idx] - msr)));
        ps[idx] = pvv;
        int j = j0 + jj;
        int dy = syi - (j>>5), dx = sxi - (j&31);
        int bkt = ((int)c_pidx[dy+31]+4)*9 + ((int)c_pidx[dx+31]+4);
        if (bkt == runb) runv += pvv;
        else {
          if (runb >= 0) atomicAdd(&sb[sr*88 + runb], runv);
          runb = bkt; runv = pvv;
        }
      }
      atomicAdd(&sb[sr*88 + runb], runv);
    }
    __syncthreads();

    #pragma unroll
    for (int ks = 0; ks < 64; ks += 8){
      uint32_t af[2][4], bf[2][2];
      #pragma unroll
      for (int mt = 0; mt < 2; mt++){
        int r0 = wm + (mt<<4) + g;
        af[mt][0] = __float_as_uint(ps[ r0   *68 + ks+tg  ]);
        af[mt][1] = __float_as_uint(ps[(r0+8)*68 + ks+tg  ]);
        af[mt][2] = __float_as_uint(ps[ r0   *68 + ks+tg+4]);
        af[mt][3] = __float_as_uint(ps[(r0+8)*68 + ks+tg+4]);
      }
      #pragma unroll
      for (int nt = 0; nt < 2; nt++){
        int n = wn + (nt<<3) + g;
        bf[nt][0] = __float_as_uint(vs[(ks+tg  )*68 + n]);
        bf[nt][1] = __float_as_uint(vs[(ks+tg+4)*68 + n]);
      }
      #pragma unroll
      for (int mt = 0; mt < 2; mt++)
        #pragma unroll
        for (int nt = 0; nt < 2; nt++)
          mma_tf32(acc[mt][nt], af[mt], bf[nt]);
    }
    __syncthreads();
  }

  float* tvs = sm + PV_TVS;
  for (int f = t; f < 88*68; f += 256) tvs[f] = 0.f;
  __syncthreads();
  for (int f = t; f < NBKT*64; f += 256){
    int c = f >> 6, d = f & 63;
    tvs[c*68 + d] = __uint_as_float(f2tf32(tv[f]));
  }
  if (t < 64){
    float ssum = 0.f;
    #pragma unroll
    for (int c = 0; c < NBKT; c++) ssum += sb[t*88 + c];
    rsv[t] = 1.0f / ssum;
  }
  __syncthreads();

  #pragma unroll
  for (int ks = 0; ks < 88; ks += 8){
    uint32_t af[2][4], bf[2][2];
    #pragma unroll
    for (int mt = 0; mt < 2; mt++){
      int r0 = wm + (mt<<4) + g;
      af[mt][0] = __float_as_uint(sb[ r0   *88 + ks+tg  ]);
      af[mt][1] = __float_as_uint(sb[(r0+8)*88 + ks+tg  ]);
      af[mt][2] = __float_as_uint(sb[ r0   *88 + ks+tg+4]);
      af[mt][3] = __float_as_uint(sb[(r0+8)*88 + ks+tg+4]);
    }
    #pragma unroll
    for (int nt = 0; nt < 2; nt++){
      int n = wn + (nt<<3) + g;
      bf[nt][0] = __float_as_uint(tvs[(ks+tg  )*68 + n]);
      bf[nt][1] = __float_as_uint(tvs[(ks+tg+4)*68 + n]);
    }
    #pragma unroll
    for (int mt = 0; mt < 2; mt++)
      #pragma unroll
      for (int nt = 0; nt < 2; nt++)
        mma_tf32(acc[mt][nt], af[mt], bf[nt]);
  }

  #pragma unroll
  for (int mt = 0; mt < 2; mt++){
    #pragma unroll
    for (int hh = 0; hh < 2; hh++){
      int r = wm + (mt<<4) + g + (hh<<3);
      float inv = rsv[r];
      #pragma unroll
      for (int nt = 0; nt < 2; nt++){
        int col = wn + (nt<<3) + (tg<<1);
        float o0 = acc[mt][nt][hh*2+0] * inv;
        float o1 = acc[mt][nt][hh*2+1] * inv;
        float* op = out + ((size_t)(b<<10) + i0 + r)*CDIM + (h<<6) + col;
        *(float2*)op = make_float2(o0, o1);
      }
    }
  }
}

// ---------------- launch ----------------------------------------------------
extern "C" void kernel_launch(void* const* d_in, const int* in_sizes, int n_in,
                              void* d_out, int out_size)
{
  const float* x0     = (const float*)d_in[0];
  const float* x1     = (const float*)d_in[1];
  const float* ln00_g = (const float*)d_in[2];
  const float* ln00_b = (const float*)d_in[3];
  const float* ln01_g = (const float*)d_in[4];
  const float* ln01_b = (const float*)d_in[5];
  const float* ln10_g = (const float*)d_in[6];
  const float* ln10_b = (const float*)d_in[7];
  const float* ln11_g = (const float*)d_in[8];
  const float* ln11_b = (const float*)d_in[9];
  const float* w_qkv0 = (const float*)d_in[10];
  const float* b_qkv0 = (const float*)d_in[11];
  const float* w_qkv1 = (const float*)d_in[12];
  const float* b_qkv1 = (const float*)d_in[13];
  const float* w_proj = (const float*)d_in[14];
  const float* b_proj = (const float*)d_in[15];
  const float* table_q= (const float*)d_in[16];
  const float* table_k= (const float*)d_in[17];
  const float* table_v= (const float*)d_in[18];
  const float* w_fc1_0= (const float*)d_in[19];
  const float* b_fc1_0= (const float*)d_in[20];
  const float* w_fc2_0= (const float*)d_in[21];
  const float* b_fc2_0= (const float*)d_in[22];
  const float* w_fc1_1= (const float*)d_in[23];
  const float* b_fc1_1= (const float*)d_in[24];
  const float* w_fc2_1= (const float*)d_in[25];
  const float* b_fc2_1= (const float*)d_in[26];

  float* out0 = (float*)d_out;
  float* out1 = (float*)d_out + (size_t)ROWS*CDIM;

  float *ln0, *ln1, *qkv0, *qkv1, *att0, *att1;
  float *lg0, *lg1, *ml0, *ml1, *hid0, *hid1;
  __nv_bfloat16 *lk0, *lk1, *lqt0, *lqt1;
  cudaGetSymbolAddress((void**)&ln0,  g_ln);     ln1  = ln0  + (size_t)ROWS*CDIM;
  cudaGetSymbolAddress((void**)&qkv0, g_qkv);    qkv1 = qkv0 + (size_t)ROWS*QKVD;
  cudaGetSymbolAddress((void**)&att0, g_att);    att1 = att0 + (size_t)ROWS*CDIM;
  cudaGetSymbolAddress((void**)&lk0,  g_lkb);    lk1  = lk0  + (size_t)BHN*LSTR;
  cudaGetSymbolAddress((void**)&lqt0, g_lqt);    lqt1 = lqt0 + (size_t)32*NBKT*NQ;
  cudaGetSymbolAddress((void**)&lg0,  g_logits); lg1  = lg0  + (size_t)32*NQ*NQ;
  cudaGetSymbolAddress((void**)&ml0,  g_ml);     ml1  = ml0  + (size_t)BHN;
  cudaGetSymbolAddress((void**)&hid0, g_hid);    hid1 = hid0 + (size_t)ROWS*HID;

  const int LOGITS_SMEM = LG_SMEM_FLOATS * 4;   // 103456 B
  const int PV_SMEM     = PV_SMEM_FLOATS * 4;
  static int attr_done = 0;
  if (!attr_done){
    cudaFuncSetAttribute(logits_kernel, cudaFuncAttributeMaxDynamicSharedMemorySize, LOGITS_SMEM);
    cudaFuncSetAttribute(pv_kernel,     cudaFuncAttributeMaxDynamicSharedMemorySize, PV_SMEM);
    attr_done = 1;
  }

  // 1. LN (both streams)
  dim3 gln(ROWS, 2);
  ln_kernel<<<gln, 128>>>(x0, x1, ln00_g, ln01_g, ln00_b, ln01_b, ln0, ln1);

  // 2. qkv GEMMs (paired, BN=128)
  {
    GemmPtrs p{{ln0, ln1},{w_qkv0, w_qkv1},{b_qkv0, b_qkv1},{nullptr,nullptr},{qkv0, qkv1}};
    dim3 gg(QKVD/128, ROWS/128, 2);
    sgemm_tf32_kernel<128><<<gg, 256>>>(p, ROWS, QKVD, CDIM, 0);
  }

  // 3. bias tables (LK row-major bf16, LQ transposed bf16)
  dim3 gbt(BHN/64, 2, 2);
  biastab_kernel<<<gbt, 256>>>(qkv0, qkv1, table_q, table_k, lk0, lk1, lqt0, lqt1);

  // 4. strip logits + direct row max
  dim3 glg(16, 64);
  logits_kernel<<<glg, 256, LOGITS_SMEM>>>(qkv0, qkv1, lk0, lk1, lqt0, lqt1,
                                           lg0, lg1, ml0, ml1);

  // 5. PV + tv table
  dim3 gpv(16, 64);
  pv_kernel<<<gpv, 256, PV_SMEM>>>(lg0, lg1, ml0, ml1, qkv0, qkv1, table_v, att0, att1);

  // 6. proj + residual (paired, BN=64)
  {
    GemmPtrs p{{att0, att1},{w_proj, w_proj},{b_proj, b_proj},{x0, x1},{out0, out1}};
    dim3 gg(CDIM/64, ROWS/128, 2);
    sgemm_tf32_kernel<64><<<gg, 256>>>(p, ROWS, CDIM, CDIM, 0);
  }

  // 7. MLP
  ln_kernel<<<gln, 128>>>(out0, out1, ln10_g, ln11_g, ln10_b, ln11_b, ln0, ln1);

  {
    GemmPtrs p{{ln0, ln1},{w_fc1_0, w_fc1_1},{b_fc1_0, b_fc1_1},{nullptr,nullptr},{hid0, hid1}};
    dim3 gg(HID/128, ROWS/128, 2);
    sgemm_tf32_kernel<128><<<gg, 256>>>(p, ROWS, HID, CDIM, 1);
  }
  {
    GemmPtrs p{{hid0, hid1},{w_fc2_0, w_fc2_1},{b_fc2_0, b_fc2_1},{out0, out1},{out0, out1}};
    dim3 gg(CDIM/64, ROWS/128, 2);
    sgemm_tf32_kernel<64><<<gg, 256>>>(p, ROWS, CDIM, HID, 0);
  }
}

// round 17
// speedup vs baseline: 1.0674x; 1.0674x over previous
#include <cuda_runtime.h>
#include <cuda_bf16.h>
#include <math.h>
#include <stdint.h>

// ---------------- problem constants ----------------
#define ROWS 4096        // B*N
#define CDIM 512
#define QKVD 1536
#define HID  2048
#define NHEAD 8
#define HD   64
#define NQ   1024
#define BHN  32768       // B*H*N
#define NBKT 81
#define LSTR 88          // bf16 bias-table row stride (16B-aligned)

// ---------------- device scratch ----------------
__device__ float g_ln    [2][ROWS*CDIM];
__device__ float g_qkv   [2][ROWS*QKVD];
__device__ float g_att   [2][ROWS*CDIM];
__device__ __nv_bfloat16 g_lkb[2][(size_t)BHN*LSTR];
__device__ __nv_bfloat16 g_lqb[2][(size_t)BHN*LSTR];
__device__ float g_logits[2][(size_t)32*NQ*NQ];
__device__ float g_ml    [2][BHN];
__device__ float g_hid   [2][(size_t)ROWS*HID];

__constant__ signed char c_pidx[63] = {
  -4,-4,-4,-4,-4,-4,-4,-4,-4,-4,-4,-4,-4,-4,-4,-4,-4,-4,-4,-4,-4,
  -3,-3,-3,-3,-3,-3,-3,
  -2,-2,
  -1,
   0,
   1,
   2, 2,
   3, 3, 3, 3, 3, 3, 3,
   4, 4, 4, 4, 4, 4, 4, 4, 4, 4, 4, 4, 4, 4, 4, 4, 4, 4, 4, 4, 4
};

__device__ __forceinline__ float fexp(float x){
  float y = x * 1.4426950408889634f;
  float n = rintf(y);
  float f = y - n;
  float p =           1.3333558e-3f;
  p = fmaf(p, f, 9.6181291e-3f);
  p = fmaf(p, f, 5.5504108e-2f);
  p = fmaf(p, f, 2.4022650e-1f);
  p = fmaf(p, f, 6.9314718e-1f);
  p = fmaf(p, f, 1.0f);
  int ni = (int)n;
  return p * __int_as_float((ni + 127) << 23);
}

__device__ __forceinline__ uint32_t f2tf32(float v){
  uint32_t r;
  asm("cvt.rna.tf32.f32 %0, %1;" : "=r"(r) : "f"(v));
  return r;
}

__device__ __forceinline__ void mma_tf32(float* c, const uint32_t* a, const uint32_t* b){
  asm volatile(
    "mma.sync.aligned.m16n8k8.row.col.f32.tf32.tf32.f32 "
    "{%0,%1,%2,%3}, {%4,%5,%6,%7}, {%8,%9}, {%0,%1,%2,%3};"
    : "+f"(c[0]), "+f"(c[1]), "+f"(c[2]), "+f"(c[3])
    : "r"(a[0]), "r"(a[1]), "r"(a[2]), "r"(a[3]), "r"(b[0]), "r"(b[1]));
}

__device__ __forceinline__ void cp16(uint32_t dst, const void* src){
  asm volatile("cp.async.cg.shared.global [%0], [%1], 16;\n" :: "r"(dst), "l"(src));
}

struct GemmPtrs {
  const float* A[2];
  const float* B[2];
  const float* bias[2];
  const float* resid[2];
  float* C[2];
};

// ---------------- layernorm (paired streams) --------------------------------
__global__ void ln_kernel(const float* __restrict__ x0, const float* __restrict__ x1,
                          const float* __restrict__ g0, const float* __restrict__ g1,
                          const float* __restrict__ be0, const float* __restrict__ be1,
                          float* __restrict__ y0, float* __restrict__ y1)
{
  int sIdx = blockIdx.y;
  const float* x  = sIdx ? x1 : x0;
  const float* gam= sIdx ? g1 : g0;
  const float* bet= sIdx ? be1 : be0;
  float* y        = sIdx ? y1 : y0;
  int row = blockIdx.x;
  int t = threadIdx.x;
  const float* xr = x + (size_t)row * CDIM;
  float4 v = *(const float4*)(xr + t*4);
  float s  = v.x + v.y + v.z + v.w;
  float s2 = v.x*v.x + v.y*v.y + v.z*v.z + v.w*v.w;
  #pragma unroll
  for (int o = 16; o > 0; o >>= 1){
    s  += __shfl_xor_sync(0xffffffffu, s , o);
    s2 += __shfl_xor_sync(0xffffffffu, s2, o);
  }
  __shared__ float rs[4], rq[4];
  if ((t & 31) == 0){ rs[t>>5] = s; rq[t>>5] = s2; }
  __syncthreads();
  s  = rs[0]+rs[1]+rs[2]+rs[3];
  s2 = rq[0]+rq[1]+rq[2]+rq[3];
  float mu   = s  * (1.0f/CDIM);
  float var  = s2 * (1.0f/CDIM) - mu*mu;
  float rstd = rsqrtf(var + 1e-5f);
  float4 g4 = *(const float4*)(gam + t*4);
  float4 b4 = *(const float4*)(bet + t*4);
  float4 o4;
  o4.x = (v.x-mu)*rstd*g4.x + b4.x;
  o4.y = (v.y-mu)*rstd*g4.y + b4.y;
  o4.z = (v.z-mu)*rstd*g4.z + b4.z;
  o4.w = (v.w-mu)*rstd*g4.w + b4.w;
  *(float4*)(y + (size_t)row*CDIM + t*4) = o4;
}

// ---------------- tf32 GEMM, 3-stage cp.async ring, BN templated ----------
template <int BN>
__global__ void __launch_bounds__(256, 2) sgemm_tf32_kernel(
    GemmPtrs p, int M, int N, int K, int gelu)
{
  constexpr int BSTR = BN + 4;
  constexpr int MT = (BN == 128) ? 4 : 2;
  constexpr int NT = 4;
  constexpr int NBCH = (BN == 128) ? 2 : 1;
  __shared__ float As[3][128*20];
  __shared__ float Bs[3][16*BSTR];
  int t = threadIdx.x;
  int z = blockIdx.z;
  const float* A     = p.A[z];
  const float* Bm    = p.B[z];
  const float* bias  = p.bias[z];
  const float* resid = p.resid[z];
  float* C           = p.C[z];

  int bn = blockIdx.x * BN;
  int bm = blockIdx.y * 128;
  int warp = t >> 5, lane = t & 31;
  int wm, wn;
  if (BN == 128){ wm = (warp >> 2) << 6; wn = (warp & 3) << 5; }
  else          { wm = (warp >> 1) << 5; wn = (warp & 1) << 5; }
  int g  = lane >> 2;
  int tg = lane & 3;

  float acc[MT][NT][4];
  #pragma unroll
  for (int mt=0;mt<MT;mt++)
    #pragma unroll
    for (int nt=0;nt<NT;nt++)
      #pragma unroll
      for (int c=0;c<4;c++) acc[mt][nt][c] = 0.f;

  const float* Ag = A + (size_t)bm * K;
  const float* Bg = Bm + bn;

  uint32_t asb[3], bsb[3];
  #pragma unroll
  for (int i = 0; i < 3; i++){
    asb[i] = (uint32_t)__cvta_generic_to_shared(&As[i][0]);
    bsb[i] = (uint32_t)__cvta_generic_to_shared(&Bs[i][0]);
  }

  int ar[2], as4[2], bkr[NBCH], bnc[NBCH];
  #pragma unroll
  for (int i = 0; i < 2; i++){
    int c = t + (i<<8);
    ar[i]  = c >> 2;  as4[i] = (c & 3) << 2;
  }
  #pragma unroll
  for (int i = 0; i < NBCH; i++){
    int c = t + (i<<8);
    if (BN == 128){ bkr[i] = c >> 5; bnc[i] = (c & 31) << 2; }
    else          { bkr[i] = c >> 4; bnc[i] = (c & 15) << 2; }
  }

  int ntiles = K >> 4;
  // prologue: tiles 0 and 1 (one commit group each)
  #pragma unroll
  for (int i = 0; i < 2; i++)
    cp16(asb[0] + ((ar[i]*20 + as4[i])<<2), Ag + (size_t)ar[i]*K + as4[i]);
  #pragma unroll
  for (int i = 0; i < NBCH; i++)
    cp16(bsb[0] + ((bkr[i]*BSTR + bnc[i])<<2), Bg + (size_t)bkr[i]*N + bnc[i]);
  asm volatile("cp.async.commit_group;\n");
  {
    int k0 = 16;
    #pragma unroll
    for (int i = 0; i < 2; i++)
      cp16(asb[1] + ((ar[i]*20 + as4[i])<<2), Ag + (size_t)ar[i]*K + k0 + as4[i]);
    #pragma unroll
    for (int i = 0; i < NBCH; i++)
      cp16(bsb[1] + ((bkr[i]*BSTR + bnc[i])<<2), Bg + (size_t)(k0 + bkr[i])*N + bnc[i]);
  }
  asm volatile("cp.async.commit_group;\n");

  int buf = 0, nbuf = 2;
  for (int it = 0; it < ntiles; it++){
    if (it + 2 < ntiles){
      int k0 = (it+2) << 4;
      #pragma unroll
      for (int i = 0; i < 2; i++)
        cp16(asb[nbuf] + ((ar[i]*20 + as4[i])<<2), Ag + (size_t)ar[i]*K + k0 + as4[i]);
      #pragma unroll
      for (int i = 0; i < NBCH; i++)
        cp16(bsb[nbuf] + ((bkr[i]*BSTR + bnc[i])<<2), Bg + (size_t)(k0 + bkr[i])*N + bnc[i]);
    }
    asm volatile("cp.async.commit_group;\n");
    asm volatile("cp.async.wait_group 2;\n");
    __syncthreads();

    const float* Ab = As[buf];
    const float* Bb = Bs[buf];
    #pragma unroll
    for (int ks = 0; ks < 16; ks += 8){
      uint32_t af[MT][4], bf[NT][2];
      #pragma unroll
      for (int mt = 0; mt < MT; mt++){
        int m = wm + (mt<<4) + g;
        af[mt][0] = __float_as_uint(Ab[ m   *20 + ks+tg  ]);
        af[mt][1] = __float_as_uint(Ab[(m+8)*20 + ks+tg  ]);
        af[mt][2] = __float_as_uint(Ab[ m   *20 + ks+tg+4]);
        af[mt][3] = __float_as_uint(Ab[(m+8)*20 + ks+tg+4]);
      }
      #pragma unroll
      for (int nt = 0; nt < NT; nt++){
        int n = wn + (nt<<3) + g;
        bf[nt][0] = __float_as_uint(Bb[(ks+tg  )*BSTR + n]);
        bf[nt][1] = __float_as_uint(Bb[(ks+tg+4)*BSTR + n]);
      }
      #pragma unroll
      for (int mt = 0; mt < MT; mt++)
        #pragma unroll
        for (int nt = 0; nt < NT; nt++)
          mma_tf32(acc[mt][nt], af[mt], bf[nt]);
    }
    __syncthreads();
    buf  = (buf  == 2) ? 0 : buf  + 1;
    nbuf = (nbuf == 2) ? 0 : nbuf + 1;
  }

  #pragma unroll
  for (int mt = 0; mt < MT; mt++){
    int row0 = bm + wm + (mt<<4) + g;
    #pragma unroll
    for (int nt = 0; nt < NT; nt++){
      int col = bn + wn + (nt<<3) + (tg<<1);
      float b0 = bias[col], b1 = bias[col+1];
      #pragma unroll
      for (int h = 0; h < 2; h++){
        int row = row0 + (h<<3);
        float r0 = acc[mt][nt][h*2+0] + b0;
        float r1 = acc[mt][nt][h*2+1] + b1;
        if (gelu){
          r0 = 0.5f*r0*(1.0f + erff(r0*0.70710678f));
          r1 = 0.5f*r1*(1.0f + erff(r1*0.70710678f));
        }
        if (resid){
          const float2 rr = *(const float2*)(resid + (size_t)row*N + col);
          r0 += rr.x; r1 += rr.y;
        }
        *(float2*)(C + (size_t)row*N + col) = make_float2(r0, r1);
      }
    }
  }
}

// ---------------- bias tables as tiled GEMM (bf16 output, stride 88) --------
__global__ void __launch_bounds__(256) biastab_kernel(
    const float* __restrict__ qkv0, const float* __restrict__ qkv1,
    const float* __restrict__ tq, const float* __restrict__ tk,
    __nv_bfloat16* __restrict__ lk0, __nv_bfloat16* __restrict__ lk1,
    __nv_bfloat16* __restrict__ lq0, __nv_bfloat16* __restrict__ lq1)
{
  __shared__ float qs[64*65];
  __shared__ float tabT[64*84];

  int t = threadIdx.x;
  int s = blockIdx.z, which = blockIdx.y;
  int base = blockIdx.x << 6;
  const float* src;
  float scl;
  if (which == 0){ src = (s == 0 ? qkv0 : qkv1);       scl = 1.0f;   }
  else           { src = (s == 0 ? qkv1 : qkv0) + 512; scl = 0.125f; }
  const float* tab = (which == 0) ? tk : tq;

  for (int idx = t; idx < NBKT*64; idx += 256){
    int c = idx >> 6, d = idx & 63;
    tabT[d*84 + c] = tab[idx];
  }
  #pragma unroll
  for (int it = 0; it < 4; it++){
    int f = t + (it<<8);
    int r = f >> 4, c4 = (f & 15) << 2;
    int rid = base + r;
    int bh = rid >> 10, n = rid & 1023;
    int b = bh >> 3, h = bh & 7;
    float4 v = *(const float4*)(src + (size_t)((b<<10)+n)*QKVD + (h<<6) + c4);
    qs[r*65+c4+0] = scl*v.x; qs[r*65+c4+1] = scl*v.y;
    qs[r*65+c4+2] = scl*v.z; qs[r*65+c4+3] = scl*v.w;
  }
  __syncthreads();

  int tx = t & 31, ty = t >> 5;
  float acc[8][3];
  #pragma unroll
  for (int i=0;i<8;i++){ acc[i][0]=0.f; acc[i][1]=0.f; acc[i][2]=0.f; }

  #pragma unroll 8
  for (int k = 0; k < 64; k++){
    float b0 = tabT[k*84 + tx];
    float b1 = tabT[k*84 + tx + 32];
    float b2 = (tx < 17) ? tabT[k*84 + tx + 64] : 0.f;
    #pragma unroll
    for (int i = 0; i < 8; i++){
      float a = qs[((ty<<3)+i)*65 + k];
      acc[i][0] = fmaf(a, b0, acc[i][0]);
      acc[i][1] = fmaf(a, b1, acc[i][1]);
      acc[i][2] = fmaf(a, b2, acc[i][2]);
    }
  }

  __nv_bfloat16* dstbase = (which == 0) ? (s == 0 ? lk0 : lk1) : (s == 0 ? lq0 : lq1);
  #pragma unroll
  for (int i = 0; i < 8; i++){
    int rid = base + (ty<<3) + i;
    __nv_bfloat16* dst = dstbase + (size_t)rid*LSTR;
    dst[tx]      = __float2bfloat16(acc[i][0]);
    dst[tx + 32] = __float2bfloat16(acc[i][1]);
    if (tx < 17) dst[tx + 64] = __float2bfloat16(acc[i][2]);
  }
}

// ---------------- strip logits: 64 rows x 1024 j, cp.async pipelined -------
#define LG_QS   0
#define LG_KS   4160
#define LG_KSZ  4352
#define LG_LKS  12864
#define LG_LQS  15680
#define LG_LQZ  2816
#define LG_RMX  21312
#define LG_SMEM_FLOATS 21568

__global__ void __launch_bounds__(256, 2) logits_kernel(
    const float* __restrict__ qkv0, const float* __restrict__ qkv1,
    const __nv_bfloat16* __restrict__ lk0, const __nv_bfloat16* __restrict__ lk1,
    const __nv_bfloat16* __restrict__ lq0, const __nv_bfloat16* __restrict__ lq1,
    float* __restrict__ lg0, float* __restrict__ lg1,
    float* __restrict__ ml0, float* __restrict__ ml1)
{
  extern __shared__ float sm[];
  float* qs = sm + LG_QS;
  __nv_bfloat16* lks = (__nv_bfloat16*)(sm + LG_LKS);
  float* rmx = sm + LG_RMX;

  int t = threadIdx.x;
  int zs = blockIdx.y;
  int s = zs >> 5;
  int bh = zs & 31; int b = bh>>3, h = bh&7;
  int i0 = blockIdx.x << 6;
  size_t rbase = ((size_t)bh)<<10;

  const float* qkv_q  = (s==0) ? qkv0 : qkv1;
  const float* qkv_kv = (s==0) ? qkv1 : qkv0;
  const __nv_bfloat16* LKb = (s==0) ? lk0 : lk1;
  const __nv_bfloat16* LQb = (s==0) ? lq0 : lq1;
  float* S  = (s==0) ? lg0 : lg1;
  float* ML = (s==0) ? ml0 : ml1;

  const float* qb = qkv_q  + (size_t)(b<<10)*QKVD + (h<<6);
  const float* kb = qkv_kv + (size_t)(b<<10)*QKVD + (h<<6) + 512;

  uint32_t ksb[2], lqsb[2];
  ksb[0]  = (uint32_t)__cvta_generic_to_shared(sm + LG_KS);
  ksb[1]  = (uint32_t)__cvta_generic_to_shared(sm + LG_KS + LG_KSZ);
  lqsb[0] = (uint32_t)__cvta_generic_to_shared(sm + LG_LQS);
  lqsb[1] = (uint32_t)__cvta_generic_to_shared(sm + LG_LQS + LG_LQZ);
  uint32_t lksb = (uint32_t)__cvta_generic_to_shared(sm + LG_LKS);

  for (int f = t; f < 704; f += 256){
    int r = f / 11, c8 = (f - r*11) << 3;
    cp16(lksb + ((r*LSTR + c8)<<1), LKb + (rbase + i0 + r)*LSTR + c8);
  }
  #pragma unroll
  for (int i = 0; i < 4; i++){
    int f = t + (i<<8);
    int r = f >> 4, c4 = (f & 15) << 2;
    cp16(ksb[0] + ((r*68 + c4)<<2), kb + (size_t)r*QKVD + c4);
  }
  for (int f = t; f < 704; f += 256){
    int r = f / 11, c8 = (f - r*11) << 3;
    cp16(lqsb[0] + ((r*LSTR + c8)<<1), LQb + (rbase + r)*LSTR + c8);
  }
  asm volatile("cp.async.commit_group;\n");

  #pragma unroll
  for (int it = 0; it < 4; it++){
    int f = t + (it<<8);
    int r = f >> 4, c4 = (f & 15) << 2;
    float4 qv = *(const float4*)(qb + (size_t)(i0+r)*QKVD + c4);
    qs[r*65+c4+0]=qv.x; qs[r*65+c4+1]=qv.y;
    qs[r*65+c4+2]=qv.z; qs[r*65+c4+3]=qv.w;
  }

  int warp = t >> 5, lane = t & 31;
  int g = lane >> 2, tg = lane & 3;
  int wm = (warp >> 2) << 5;
  int wn = (warp & 3) << 4;

  float rml[2][2];
  rml[0][0] = rml[0][1] = rml[1][0] = rml[1][1] = -1e30f;

  for (int jt = 0; jt < 16; jt++){
    int buf = jt & 1;
    if (jt + 1 < 16){
      int j0n = (jt+1) << 6;
      int nb = (jt+1) & 1;
      #pragma unroll
      for (int i = 0; i < 4; i++){
        int f = t + (i<<8);
        int r = f >> 4, c4 = (f & 15) << 2;
        cp16(ksb[nb] + ((r*68 + c4)<<2), kb + (size_t)(j0n+r)*QKVD + c4);
      }
      for (int f = t; f < 704; f += 256){
        int r = f / 11, c8 = (f - r*11) << 3;
        cp16(lqsb[nb] + ((r*LSTR + c8)<<1), LQb + (rbase + j0n + r)*LSTR + c8);
      }
    }
    asm volatile("cp.async.commit_group;\n");
    asm volatile("cp.async.wait_group 1;\n");
    __syncthreads();

    const float* ks = sm + LG_KS + buf*LG_KSZ;
    const __nv_bfloat16* lqs = (const __nv_bfloat16*)(sm + LG_LQS + buf*LG_LQZ);
    int j0 = jt << 6;

    float acc[2][2][4];
    #pragma unroll
    for (int mt=0;mt<2;mt++)
      #pragma unroll
      for (int nt=0;nt<2;nt++)
        #pragma unroll
        for (int c=0;c<4;c++) acc[mt][nt][c]=0.f;

    #pragma unroll
    for (int kk = 0; kk < 64; kk += 8){
      uint32_t af[2][4], bf[2][2];
      #pragma unroll
      for (int mt = 0; mt < 2; mt++){
        int r0 = wm + (mt<<4) + g;
        af[mt][0] = __float_as_uint(qs[ r0   *65 + kk+tg  ]);
        af[mt][1] = __float_as_uint(qs[(r0+8)*65 + kk+tg  ]);
        af[mt][2] = __float_as_uint(qs[ r0   *65 + kk+tg+4]);
        af[mt][3] = __float_as_uint(qs[(r0+8)*65 + kk+tg+4]);
      }
      #pragma unroll
      for (int nt = 0; nt < 2; nt++){
        int n = wn + (nt<<3) + g;
        bf[nt][0] = __float_as_uint(ks[n*68 + kk+tg  ]);
        bf[nt][1] = __float_as_uint(ks[n*68 + kk+tg+4]);
      }
      #pragma unroll
      for (int mt = 0; mt < 2; mt++)
        #pragma unroll
        for (int nt = 0; nt < 2; nt++)
          mma_tf32(acc[mt][nt], af[mt], bf[nt]);
    }

    #pragma unroll
    for (int mt = 0; mt < 2; mt++){
      #pragma unroll
      for (int hh = 0; hh < 2; hh++){
        int il = wm + (mt<<4) + g + (hh<<3);
        int i = i0 + il;
        int yi = i >> 5, xi = i & 31;
        const __nv_bfloat16* lkrow = lks + il*LSTR;
        #pragma unroll
        for (int nt = 0; nt < 2; nt++){
          int jl = wn + (nt<<3) + (tg<<1);
          int j = j0 + jl;
          int dy0 = yi - (j>>5),     dx0 = xi - (j&31);
          int dy1 = yi - ((j+1)>>5), dx1 = xi - ((j+1)&31);
          int bkt0 = ((int)c_pidx[dy0+31]+4)*9 + ((int)c_pidx[dx0+31]+4);
          int bkt1 = ((int)c_pidx[dy1+31]+4)*9 + ((int)c_pidx[dx1+31]+4);
          float v0 = acc[mt][nt][hh*2+0]*0.125f + __bfloat162float(lkrow[bkt0])
                   + __bfloat162float(lqs[jl*LSTR + 80 - bkt0]);
          float v1 = acc[mt][nt][hh*2+1]*0.125f + __bfloat162float(lkrow[bkt1])
                   + __bfloat162float(lqs[(jl+1)*LSTR + 80 - bkt1]);
          *(float2*)(S + (rbase + i)*NQ + j) = make_float2(v0, v1);
          rml[mt][hh] = fmaxf(rml[mt][hh], fmaxf(v0, v1));
        }
      }
    }
    __syncthreads();
  }

  #pragma unroll
  for (int mt = 0; mt < 2; mt++){
    #pragma unroll
    for (int hh = 0; hh < 2; hh++){
      float rm = rml[mt][hh];
      rm = fmaxf(rm, __shfl_xor_sync(0xffffffffu, rm, 1));
      rm = fmaxf(rm, __shfl_xor_sync(0xffffffffu, rm, 2));
      if (tg == 0){
        int il = wm + (mt<<4) + g + (hh<<3);
        rmx[(il<<2) + (warp & 3)] = rm;
      }
    }
  }
  __syncthreads();
  if (t < 64){
    float m = fmaxf(fmaxf(rmx[t<<2], rmx[(t<<2)+1]),
                    fmaxf(rmx[(t<<2)+2], rmx[(t<<2)+3]));
    ML[rbase + i0 + t] = m;
  }
}

// ---------------- PV: cp.async double-buffered + scatter + tv-GEMM ---------
#define PV_S    0
#define PV_V    8704
#define PV_SB   17408
#define PV_MROW 23040
#define PV_RSV  23104
#define PV_TVS  8704
#define PV_SMEM_FLOATS 23168

__global__ void __launch_bounds__(256) pv_kernel(
    const float* __restrict__ lg0, const float* __restrict__ lg1,
    const float* __restrict__ ml0, const float* __restrict__ ml1,
    const float* __restrict__ qkv0, const float* __restrict__ qkv1,
    const float* __restrict__ tv,
    float* __restrict__ att0, float* __restrict__ att1)
{
  extern __shared__ float sm[];
  float* sb  = sm + PV_SB;
  float* mrow= sm + PV_MROW;
  float* rsv = sm + PV_RSV;

  int t = threadIdx.x;
  int zy = blockIdx.y;
  int s = zy >> 5;
  int bh = zy & 31; int b = bh>>3, h = bh&7;
  int i0 = blockIdx.x << 6;
  size_t rb2 = (((size_t)bh)<<10) + i0;

  const float* S  = (s==0) ? lg0 : lg1;
  const float* ml = (s==0) ? ml0 : ml1;
  const float* qkv_kv = (s==0) ? qkv1 : qkv0;
  float* out = (s==0) ? att0 : att1;

  if (t < 64) mrow[t] = ml[rb2 + t];
  for (int f = t; f < 64*88; f += 256) sb[f] = 0.f;

  const float* vb = qkv_kv + ((size_t)(b<<10))*QKVD + (h<<6) + 1024;

  uint32_t sbs[2], vbs[2];
  sbs[0] = (uint32_t)__cvta_generic_to_shared(sm + PV_S);
  sbs[1] = (uint32_t)__cvta_generic_to_shared(sm + PV_S + 4352);
  vbs[0] = (uint32_t)__cvta_generic_to_shared(sm + PV_V);
  vbs[1] = (uint32_t)__cvta_generic_to_shared(sm + PV_V + 4352);

  int cr[4], cc4[4];
  #pragma unroll
  for (int i = 0; i < 4; i++){
    int f = t + (i<<8);
    cr[i] = f >> 4; cc4[i] = (f & 15) << 2;
  }

  #pragma unroll
  for (int i = 0; i < 4; i++){
    cp16(sbs[0] + ((cr[i]*68 + cc4[i])<<2), S + (rb2 + cr[i])*NQ + cc4[i]);
    cp16(vbs[0] + ((cr[i]*68 + cc4[i])<<2), vb + (size_t)cr[i]*QKVD + cc4[i]);
  }
  asm volatile("cp.async.commit_group;\n");
  __syncthreads();

  int warp = t >> 5, lane = t & 31;
  int g = lane >> 2, tg = lane & 3;
  int wm = (warp >> 2) << 5;
  int wn = (warp & 3) << 4;

  float acc[2][2][4];
  #pragma unroll
  for (int mt=0;mt<2;mt++)
    #pragma unroll
    for (int nt=0;nt<2;nt++)
      #pragma unroll
      for (int c=0;c<4;c++) acc[mt][nt][c]=0.f;

  int sr = t >> 2;
  int q0 = (t & 3) << 4;
  int iglob = i0 + sr;
  int syi = iglob >> 5, sxi = iglob & 31;
  float msr = mrow[sr];

  for (int jt = 0; jt < 16; jt++){
    int buf = jt & 1;
    if (jt + 1 < 16){
      int j0n = (jt+1) << 6;
      int nb = (jt+1) & 1;
      #pragma unroll
      for (int i = 0; i < 4; i++){
        cp16(sbs[nb] + ((cr[i]*68 + cc4[i])<<2), S + (rb2 + cr[i])*NQ + j0n + cc4[i]);
        cp16(vbs[nb] + ((cr[i]*68 + cc4[i])<<2), vb + (size_t)(j0n + cr[i])*QKVD + cc4[i]);
      }
    }
    asm volatile("cp.async.commit_group;\n");
    asm volatile("cp.async.wait_group 1;\n");
    __syncthreads();

    float* ps = sm + PV_S + buf*4352;
    float* vs = sm + PV_V + buf*4352;
    int j0 = jt << 6;

    {
      float runv = 0.f; int runb = -1;
      #pragma unroll
      for (int q = 0; q < 16; q++){
        int jj = q0 + q;
        int idx = sr*68 + jj;
        float pvv = __uint_as_float(f2tf32(fexp(ps[idx] - msr)));
        ps[idx] = pvv;
        int j = j0 + jj;
        int dy = syi - (j>>5), dx = sxi - (j&31);
        int bkt = ((int)c_pidx[dy+31]+4)*9 + ((int)c_pidx[dx+31]+4);
        if (bkt == runb) runv += pvv;
        else {
          if (runb >= 0) atomicAdd(&sb[sr*88 + runb], runv);
          runb = bkt; runv = pvv;
        }
      }
      atomicAdd(&sb[sr*88 + runb], runv);
    }
    __syncthreads();

    #pragma unroll
    for (int ks = 0; ks < 64; ks += 8){
      uint32_t af[2][4], bf[2][2];
      #pragma unroll
      for (int mt = 0; mt < 2; mt++){
        int r0 = wm + (mt<<4) + g;
        af[mt][0] = __float_as_uint(ps[ r0   *68 + ks+tg  ]);
        af[mt][1] = __float_as_uint(ps[(r0+8)*68 + ks+tg  ]);
        af[mt][2] = __float_as_uint(ps[ r0   *68 + ks+tg+4]);
        af[mt][3] = __float_as_uint(ps[(r0+8)*68 + ks+tg+4]);
      }
      #pragma unroll
      for (int nt = 0; nt < 2; nt++){
        int n = wn + (nt<<3) + g;
        bf[nt][0] = __float_as_uint(vs[(ks+tg  )*68 + n]);
        bf[nt][1] = __float_as_uint(vs[(ks+tg+4)*68 + n]);
      }
      #pragma unroll
      for (int mt = 0; mt < 2; mt++)
        #pragma unroll
        for (int nt = 0; nt < 2; nt++)
          mma_tf32(acc[mt][nt], af[mt], bf[nt]);
    }
    __syncthreads();
  }

  float* tvs = sm + PV_TVS;
  for (int f = t; f < 88*68; f += 256) tvs[f] = 0.f;
  __syncthreads();
  for (int f = t; f < NBKT*64; f += 256){
    int c = f >> 6, d = f & 63;
    tvs[c*68 + d] = __uint_as_float(f2tf32(tv[f]));
  }
  if (t < 64){
    float ssum = 0.f;
    #pragma unroll
    for (int c = 0; c < NBKT; c++) ssum += sb[t*88 + c];
    rsv[t] = 1.0f / ssum;
  }
  __syncthreads();

  #pragma unroll
  for (int ks = 0; ks < 88; ks += 8){
    uint32_t af[2][4], bf[2][2];
    #pragma unroll
    for (int mt = 0; mt < 2; mt++){
      int r0 = wm + (mt<<4) + g;
      af[mt][0] = __float_as_uint(sb[ r0   *88 + ks+tg  ]);
      af[mt][1] = __float_as_uint(sb[(r0+8)*88 + ks+tg  ]);
      af[mt][2] = __float_as_uint(sb[ r0   *88 + ks+tg+4]);
      af[mt][3] = __float_as_uint(sb[(r0+8)*88 + ks+tg+4]);
    }
    #pragma unroll
    for (int nt = 0; nt < 2; nt++){
      int n = wn + (nt<<3) + g;
      bf[nt][0] = __float_as_uint(tvs[(ks+tg  )*68 + n]);
      bf[nt][1] = __float_as_uint(tvs[(ks+tg+4)*68 + n]);
    }
    #pragma unroll
    for (int mt = 0; mt < 2; mt++)
      #pragma unroll
      for (int nt = 0; nt < 2; nt++)
        mma_tf32(acc[mt][nt], af[mt], bf[nt]);
  }

  #pragma unroll
  for (int mt = 0; mt < 2; mt++){
    #pragma unroll
    for (int hh = 0; hh < 2; hh++){
      int r = wm + (mt<<4) + g + (hh<<3);
      float inv = rsv[r];
      #pragma unroll
      for (int nt = 0; nt < 2; nt++){
        int col = wn + (nt<<3) + (tg<<1);
        float o0 = acc[mt][nt][hh*2+0] * inv;
        float o1 = acc[mt][nt][hh*2+1] * inv;
        float* op = out + ((size_t)(b<<10) + i0 + r)*CDIM + (h<<6) + col;
        *(float2*)op = make_float2(o0, o1);
      }
    }
  }
}

// ---------------- launch ----------------------------------------------------
extern "C" void kernel_launch(void* const* d_in, const int* in_sizes, int n_in,
                              void* d_out, int out_size)
{
  const float* x0     = (const float*)d_in[0];
  const float* x1     = (const float*)d_in[1];
  const float* ln00_g = (const float*)d_in[2];
  const float* ln00_b = (const float*)d_in[3];
  const float* ln01_g = (const float*)d_in[4];
  const float* ln01_b = (const float*)d_in[5];
  const float* ln10_g = (const float*)d_in[6];
  const float* ln10_b = (const float*)d_in[7];
  const float* ln11_g = (const float*)d_in[8];
  const float* ln11_b = (const float*)d_in[9];
  const float* w_qkv0 = (const float*)d_in[10];
  const float* b_qkv0 = (const float*)d_in[11];
  const float* w_qkv1 = (const float*)d_in[12];
  const float* b_qkv1 = (const float*)d_in[13];
  const float* w_proj = (const float*)d_in[14];
  const float* b_proj = (const float*)d_in[15];
  const float* table_q= (const float*)d_in[16];
  const float* table_k= (const float*)d_in[17];
  const float* table_v= (const float*)d_in[18];
  const float* w_fc1_0= (const float*)d_in[19];
  const float* b_fc1_0= (const float*)d_in[20];
  const float* w_fc2_0= (const float*)d_in[21];
  const float* b_fc2_0= (const float*)d_in[22];
  const float* w_fc1_1= (const float*)d_in[23];
  const float* b_fc1_1= (const float*)d_in[24];
  const float* w_fc2_1= (const float*)d_in[25];
  const float* b_fc2_1= (const float*)d_in[26];

  float* out0 = (float*)d_out;
  float* out1 = (float*)d_out + (size_t)ROWS*CDIM;

  float *ln0, *ln1, *qkv0, *qkv1, *att0, *att1;
  float *lg0, *lg1, *ml0, *ml1, *hid0, *hid1;
  __nv_bfloat16 *lk0, *lk1, *lq0, *lq1;
  cudaGetSymbolAddress((void**)&ln0,  g_ln);     ln1  = ln0  + (size_t)ROWS*CDIM;
  cudaGetSymbolAddress((void**)&qkv0, g_qkv);    qkv1 = qkv0 + (size_t)ROWS*QKVD;
  cudaGetSymbolAddress((void**)&att0, g_att);    att1 = att0 + (size_t)ROWS*CDIM;
  cudaGetSymbolAddress((void**)&lk0,  g_lkb);    lk1  = lk0  + (size_t)BHN*LSTR;
  cudaGetSymbolAddress((void**)&lq0,  g_lqb);    lq1  = lq0  + (size_t)BHN*LSTR;
  cudaGetSymbolAddress((void**)&lg0,  g_logits); lg1  = lg0  + (size_t)32*NQ*NQ;
  cudaGetSymbolAddress((void**)&ml0,  g_ml);     ml1  = ml0  + (size_t)BHN;
  cudaGetSymbolAddress((void**)&hid0, g_hid);    hid1 = hid0 + (size_t)ROWS*HID;

  const int LOGITS_SMEM = LG_SMEM_FLOATS * 4;   // 86272 B
  const int PV_SMEM     = PV_SMEM_FLOATS * 4;
  static int attr_done = 0;
  if (!attr_done){
    cudaFuncSetAttribute(logits_kernel, cudaFuncAttributeMaxDynamicSharedMemorySize, LOGITS_SMEM);
    cudaFuncSetAttribute(pv_kernel,     cudaFuncAttributeMaxDynamicSharedMemorySize, PV_SMEM);
    attr_done = 1;
  }

  // 1. LN (both streams)
  dim3 gln(ROWS, 2);
  ln_kernel<<<gln, 128>>>(x0, x1, ln00_g, ln01_g, ln00_b, ln01_b, ln0, ln1);

  // 2. qkv GEMMs (paired, BN=128)
  {
    GemmPtrs p{{ln0, ln1},{w_qkv0, w_qkv1},{b_qkv0, b_qkv1},{nullptr,nullptr},{qkv0, qkv1}};
    dim3 gg(QKVD/128, ROWS/128, 2);
    sgemm_tf32_kernel<128><<<gg, 256>>>(p, ROWS, QKVD, CDIM, 0);
  }

  // 3. bias tables (bf16, stride 88)
  dim3 gbt(BHN/64, 2, 2);
  biastab_kernel<<<gbt, 256>>>(qkv0, qkv1, table_q, table_k, lk0, lk1, lq0, lq1);

  // 4. strip logits + direct row max
  dim3 glg(16, 64);
  logits_kernel<<<glg, 256, LOGITS_SMEM>>>(qkv0, qkv1, lk0, lk1, lq0, lq1,
                                           lg0, lg1, ml0, ml1);

  // 5. PV + tv table
  dim3 gpv(16, 64);
  pv_kernel<<<gpv, 256, PV_SMEM>>>(lg0, lg1, ml0, ml1, qkv0, qkv1, table_v, att0, att1);

  // 6. proj + residual (paired, BN=64)
  {
    GemmPtrs p{{att0, att1},{w_proj, w_proj},{b_proj, b_proj},{x0, x1},{out0, out1}};
    dim3 gg(CDIM/64, ROWS/128, 2);
    sgemm_tf32_kernel<64><<<gg, 256>>>(p, ROWS, CDIM, CDIM, 0);
  }

  // 7. MLP
  ln_kernel<<<gln, 128>>>(out0, out1, ln10_g, ln11_g, ln10_b, ln11_b, ln0, ln1);

  {
    GemmPtrs p{{ln0, ln1},{w_fc1_0, w_fc1_1},{b_fc1_0, b_fc1_1},{nullptr,nullptr},{hid0, hid1}};
    dim3 gg(HID/128, ROWS/128, 2);
    sgemm_tf32_kernel<128><<<gg, 256>>>(p, ROWS, HID, CDIM, 1);
  }
  {
    GemmPtrs p{{hid0, hid1},{w_fc2_0, w_fc2_1},{b_fc2_0, b_fc2_1},{out0, out1},{out0, out1}};
    dim3 gg(CDIM/64, ROWS/128, 2);
    sgemm_tf32_kernel<64><<<gg, 256>>>(p, ROWS, CDIM, HID, 0);
  }
}